// round 14
// baseline (speedup 1.0000x reference)
#include <cuda_runtime.h>
#include <math.h>

#define BB 128
#define HH 4
#define NN 4096
#define WW 128
#define CTRL 1560          // H*(3*W+6)
#define EPSF 1e-8f
#define T 512              // threads per block (16 warps)

__device__ __forceinline__ float softplusf(float x) {
    return (x > 20.f) ? x : log1pf(expf(x));
}
__device__ __forceinline__ float sigmoidf(float x) {
    return 1.f / (1.f + expf(-x));
}

// 128-bit global load with L2 evict_last cache-hint policy
__device__ __forceinline__ float4 ldg_evict_last(const float* p, unsigned long long pol) {
    float4 v;
    asm volatile("ld.global.nc.L2::cache_hint.v4.f32 {%0,%1,%2,%3}, [%4], %5;"
                 : "=f"(v.x), "=f"(v.y), "=f"(v.z), "=f"(v.w)
                 : "l"(p), "l"(pol));
    return v;
}

// block-wide reductions over 512 threads (16 warps)
__device__ __forceinline__ float blockReduceSum16(float v, float* red, int tid) {
    int lane = tid & 31, wid = tid >> 5;
    #pragma unroll
    for (int o = 16; o; o >>= 1) v += __shfl_xor_sync(0xFFFFFFFFu, v, o);
    if (lane == 0) red[wid] = v;
    __syncthreads();
    float r = (tid < 16) ? red[tid] : 0.f;
    if (wid == 0) {
        #pragma unroll
        for (int o = 16; o; o >>= 1) r += __shfl_xor_sync(0xFFFFFFFFu, r, o);
        if (lane == 0) red[0] = r;
    }
    __syncthreads();
    float outv = red[0];
    __syncthreads();
    return outv;
}
__device__ __forceinline__ float blockReduceMax16(float v, float* red, int tid) {
    int lane = tid & 31, wid = tid >> 5;
    #pragma unroll
    for (int o = 16; o; o >>= 1) v = fmaxf(v, __shfl_xor_sync(0xFFFFFFFFu, v, o));
    if (lane == 0) red[wid] = v;
    __syncthreads();
    float r = (tid < 16) ? red[tid] : -INFINITY;
    if (wid == 0) {
        #pragma unroll
        for (int o = 16; o; o >>= 1) r = fmaxf(r, __shfl_xor_sync(0xFFFFFFFFu, r, o));
        if (lane == 0) red[0] = r;
    }
    __syncthreads();
    float outv = red[0];
    __syncthreads();
    return outv;
}

// compute one 4-row group's scores from preloaded m[4]
#define SCORE_GROUP(mv, nidx)                                                                   \
    {                                                                                           \
        float m2 = 0.f, d0 = 0.f, d1 = 0.f, d2 = 0.f, d3 = 0.f;                                 \
        _Pragma("unroll")                                                                       \
        for (int i = 0; i < 4; i++) {                                                           \
            m2 = fmaf(mv[i].x, mv[i].x, fmaf(mv[i].y, mv[i].y, fmaf(mv[i].z, mv[i].z, fmaf(mv[i].w, mv[i].w, m2)))); \
            d0 = fmaf(mv[i].x, kk[0][i].x, fmaf(mv[i].y, kk[0][i].y, fmaf(mv[i].z, kk[0][i].z, fmaf(mv[i].w, kk[0][i].w, d0)))); \
            d1 = fmaf(mv[i].x, kk[1][i].x, fmaf(mv[i].y, kk[1][i].y, fmaf(mv[i].z, kk[1][i].z, fmaf(mv[i].w, kk[1][i].w, d1)))); \
            d2 = fmaf(mv[i].x, kk[2][i].x, fmaf(mv[i].y, kk[2][i].y, fmaf(mv[i].z, kk[2][i].z, fmaf(mv[i].w, kk[2][i].w, d2)))); \
            d3 = fmaf(mv[i].x, kk[3][i].x, fmaf(mv[i].y, kk[3][i].y, fmaf(mv[i].z, kk[3][i].z, fmaf(mv[i].w, kk[3][i].w, d3)))); \
        }                                                                                       \
        _Pragma("unroll")                                                                       \
        for (int o = 4; o; o >>= 1) {                                                           \
            m2 += __shfl_xor_sync(0xFFFFFFFFu, m2, o);                                          \
            d0 += __shfl_xor_sync(0xFFFFFFFFu, d0, o);                                          \
            d1 += __shfl_xor_sync(0xFFFFFFFFu, d1, o);                                          \
            d2 += __shfl_xor_sync(0xFFFFFFFFu, d2, o);                                          \
            d3 += __shfl_xor_sync(0xFFFFFFFFu, d3, o);                                          \
        }                                                                                       \
        if (sub == 0) {                                                                         \
            float nm = sqrtf(m2);                                                               \
            s[0 * NN + (nidx)] = d0 / (kn[0] * nm + EPSF);                                      \
            s[1 * NN + (nidx)] = d1 / (kn[1] * nm + EPSF);                                      \
            s[2 * NN + (nidx)] = d2 / (kn[2] * nm + EPSF);                                      \
            s[3 * NN + (nidx)] = d3 / (kn[3] * nm + EPSF);                                      \
        }                                                                                       \
    }

// ============ ONE fused kernel: block b handles batch b end-to-end ==========
__global__ __launch_bounds__(T) void fused_writehead(
    const float* __restrict__ memory,     // [B,N,W]
    const float* __restrict__ controls,   // [B,CTRL]
    const float* __restrict__ bias,       // [H,N]
    float* __restrict__ out)              // [B,N,W]
{
    extern __shared__ float s[];          // [HH*NN] scores -> weights (64 KB)
    __shared__ float kbuf[HH * WW];
    __shared__ float ebuf[HH * WW];
    __shared__ float wbuf[HH * WW];
    __shared__ float red[16];
    __shared__ float kn_s[HH], beta_s[HH], gate_s[HH], gamma_s[HH];
    __shared__ float sh_s[HH][3];

    const int b    = blockIdx.x;
    const int tid  = threadIdx.x;
    const int lane = tid & 31;
    const int warp = tid >> 5;

    // ---------------- prologue: control activations (1 value/thread) -------
    {
        const float* c = controls + b * CTRL;
        int h = tid >> 7, w = tid & 127;
        float kv = tanhf(c[h * WW + w]);
        kbuf[tid] = kv;
        ebuf[tid] = sigmoidf(c[512 + h * WW + w]);
        wbuf[tid] = tanhf(c[1024 + h * WW + w]);

        float ss = kv * kv;
        #pragma unroll
        for (int o = 16; o; o >>= 1) ss += __shfl_xor_sync(0xFFFFFFFFu, ss, o);
        if (lane == 0) red[warp] = ss;
        __syncthreads();
        if (tid < HH) {
            int h4 = tid * 4;
            kn_s[tid]    = sqrtf(red[h4] + red[h4 + 1] + red[h4 + 2] + red[h4 + 3]);
            beta_s[tid]  = softplusf(c[1536 + tid]);
            gate_s[tid]  = sigmoidf(c[1540 + tid]);
            gamma_s[tid] = 1.f + softplusf(c[1556 + tid]);
            float a0 = c[1544 + tid * 3 + 0];
            float a1 = c[1544 + tid * 3 + 1];
            float a2 = c[1544 + tid * 3 + 2];
            float m = fmaxf(a0, fmaxf(a1, a2));
            float e0 = expf(a0 - m), e1 = expf(a1 - m), e2 = expf(a2 - m);
            float inv = 1.f / (e0 + e1 + e2);
            sh_s[tid][0] = e0 * inv; sh_s[tid][1] = e1 * inv; sh_s[tid][2] = e2 * inv;
        }
        __syncthreads();
    }

    const float* memb = memory + (size_t)b * NN * WW;

    unsigned long long pol;
    asm volatile("createpolicy.fractional.L2::evict_last.b64 %0, 1.0;" : "=l"(pol));

    // ---------------- pass 1: cosine scores into smem -----------------------
    // 8 lanes/row; two 4-row groups per iter, 8 LDG.128 front-batched.
    // Slabs >= 40 (rows >= 2560, ~98 MB chip-wide) loaded with L2 evict_last
    // so pass 2 (which starts at slab 63 and walks down) hits them.
    {
        const int sub  = lane & 7;
        const int rsel = lane >> 3;
        float4 kk[HH][4];
        float  kn[HH];
        #pragma unroll
        for (int h = 0; h < HH; h++) {
            const float* kp = &kbuf[h * WW + sub * 16];
            #pragma unroll
            for (int i = 0; i < 4; i++) kk[h][i] = *(const float4*)(kp + 4 * i);
            kn[h] = kn_s[h];
        }
        for (int it = 0; it < 40; it += 2) {
            int nA = it * 64 + warp * 4 + rsel;
            int nB = nA + 64;
            const float* rpA = memb + (size_t)nA * WW + sub * 16;
            const float* rpB = memb + (size_t)nB * WW + sub * 16;
            float4 a[4], bb[4];
            #pragma unroll
            for (int i = 0; i < 4; i++) a[i]  = *(const float4*)(rpA + 4 * i);
            #pragma unroll
            for (int i = 0; i < 4; i++) bb[i] = *(const float4*)(rpB + 4 * i);
            SCORE_GROUP(a, nA)
            SCORE_GROUP(bb, nB)
        }
        for (int it = 40; it < 64; it += 2) {
            int nA = it * 64 + warp * 4 + rsel;
            int nB = nA + 64;
            const float* rpA = memb + (size_t)nA * WW + sub * 16;
            const float* rpB = memb + (size_t)nB * WW + sub * 16;
            float4 a[4], bb[4];
            #pragma unroll
            for (int i = 0; i < 4; i++) a[i]  = ldg_evict_last(rpA + 4 * i, pol);
            #pragma unroll
            for (int i = 0; i < 4; i++) bb[i] = ldg_evict_last(rpB + 4 * i, pol);
            SCORE_GROUP(a, nA)
            SCORE_GROUP(bb, nB)
        }
        __syncthreads();
    }

    // ------------- weight pipeline per head (all in smem) -------------------
    for (int h = 0; h < HH; h++) {
        float beta  = beta_s[h];
        float gate  = gate_s[h];
        float gamma = gamma_s[h];
        float s0 = sh_s[h][0], s1 = sh_s[h][1], s2 = sh_s[h][2];
        const float* bp = bias + h * NN;
        float* sh = s + h * NN;

        float bv[8], bmax = -INFINITY;
        #pragma unroll
        for (int k = 0; k < 8; k++) {
            bv[k] = bp[tid + k * T];
            bmax = fmaxf(bmax, bv[k]);
        }
        bmax = blockReduceMax16(bmax, red, tid);
        float bs = 0.f;
        #pragma unroll
        for (int k = 0; k < 8; k++) { bv[k] = __expf(bv[k] - bmax); bs += bv[k]; }
        bs = blockReduceSum16(bs, red, tid);
        float invB = 1.f / bs;

        float v[8], mx = -INFINITY;
        #pragma unroll
        for (int k = 0; k < 8; k++) {
            v[k] = sh[tid + k * T] * beta;
            mx = fmaxf(mx, v[k]);
        }
        mx = blockReduceMax16(mx, red, tid);
        float sum = 0.f;
        #pragma unroll
        for (int k = 0; k < 8; k++) { v[k] = __expf(v[k] - mx); sum += v[k]; }
        sum = blockReduceSum16(sum, red, tid);
        float invS = 1.f / sum;
        float omg = 1.f - gate;
        #pragma unroll
        for (int k = 0; k < 8; k++) {
            int n = tid + k * T;
            sh[n] = gate * v[k] * invS + omg * bv[k] * invB;   // w_interp
        }
        __syncthreads();

        float t = 0.f, ws[8];
        #pragma unroll
        for (int k = 0; k < 8; k++) {
            int n = tid + k * T;
            float wsh = s0 * sh[(n - 1) & (NN - 1)] + s1 * sh[n] + s2 * sh[(n + 1) & (NN - 1)];
            float p = exp2f(gamma * __log2f(wsh));   // wsh==0 -> 0, matches fp32 underflow
            ws[k] = p;
            t += p;
        }
        t = blockReduceSum16(t, red, tid);
        float invT = 1.f / (t + EPSF);
        #pragma unroll
        for (int k = 0; k < 8; k++)
            sh[tid + k * T] = ws[k] * invT;          // final write_dist
    }
    __syncthreads();

    // ---------------- pass 2: erase/update/write ----------------------------
    // Same slab mapping as pass 1, descending: all warps start on the hottest
    // (most recently read, evict_last-protected) lines and walk down.
    {
        float4 ea[HH], wa[HH];
        #pragma unroll
        for (int h = 0; h < HH; h++) {
            ea[h] = *(const float4*)&ebuf[h * WW + lane * 4];
            wa[h] = *(const float4*)&wbuf[h * WW + lane * 4];
        }
        float* outb = out + (size_t)b * NN * WW;
        for (int j = 31; j >= 0; j--) {
            int baseA = (2 * j + 1) * 64 + warp * 4;   // hotter slab first
            int baseB = (2 * j) * 64 + warp * 4;
            float4 m[8];
            #pragma unroll
            for (int r = 0; r < 4; r++)
                m[r] = __ldcs((const float4*)(memb + (size_t)(baseA + r) * WW + lane * 4));
            #pragma unroll
            for (int r = 0; r < 4; r++)
                m[4 + r] = __ldcs((const float4*)(memb + (size_t)(baseB + r) * WW + lane * 4));
            float4 wdA[HH], wdB[HH];
            #pragma unroll
            for (int h = 0; h < HH; h++) {
                wdA[h] = *(const float4*)&s[h * NN + baseA];
                wdB[h] = *(const float4*)&s[h * NN + baseB];
            }
            #pragma unroll
            for (int r = 0; r < 8; r++) {
                float w0, w1, w2, w3;
                int row;
                if (r < 4) {
                    row = baseA + r;
                    w0 = (&wdA[0].x)[r]; w1 = (&wdA[1].x)[r];
                    w2 = (&wdA[2].x)[r]; w3 = (&wdA[3].x)[r];
                } else {
                    row = baseB + (r - 4);
                    w0 = (&wdB[0].x)[r - 4]; w1 = (&wdB[1].x)[r - 4];
                    w2 = (&wdB[2].x)[r - 4]; w3 = (&wdB[3].x)[r - 4];
                }
                float4 o;
                o.x = m[r].x * ((1.f - w0*ea[0].x) * (1.f - w1*ea[1].x) * (1.f - w2*ea[2].x) * (1.f - w3*ea[3].x))
                    + (w0*wa[0].x + w1*wa[1].x + w2*wa[2].x + w3*wa[3].x);
                o.y = m[r].y * ((1.f - w0*ea[0].y) * (1.f - w1*ea[1].y) * (1.f - w2*ea[2].y) * (1.f - w3*ea[3].y))
                    + (w0*wa[0].y + w1*wa[1].y + w2*wa[2].y + w3*wa[3].y);
                o.z = m[r].z * ((1.f - w0*ea[0].z) * (1.f - w1*ea[1].z) * (1.f - w2*ea[2].z) * (1.f - w3*ea[3].z))
                    + (w0*wa[0].z + w1*wa[1].z + w2*wa[2].z + w3*wa[3].z);
                o.w = m[r].w * ((1.f - w0*ea[0].w) * (1.f - w1*ea[1].w) * (1.f - w2*ea[2].w) * (1.f - w3*ea[3].w))
                    + (w0*wa[0].w + w1*wa[1].w + w2*wa[2].w + w3*wa[3].w);
                __stcs((float4*)(outb + (size_t)row * WW + lane * 4), o);
            }
        }
    }
}

// ---------------------------------------------------------------------------
extern "C" void kernel_launch(void* const* d_in, const int* in_sizes, int n_in,
                              void* d_out, int out_size) {
    const float* memory   = (const float*)d_in[0];   // [B,N,W]
    const float* controls = (const float*)d_in[1];   // [B,CTRL]
    const float* bias     = (const float*)d_in[2];   // [1,H,N]
    float* out = (float*)d_out;                      // [B,N,W]

    const int smem = HH * NN * sizeof(float);        // 64 KB dynamic
    cudaFuncSetAttribute(fused_writehead,
                         cudaFuncAttributeMaxDynamicSharedMemorySize, smem);
    fused_writehead<<<BB, T, smem>>>(memory, controls, bias, out);
}